// round 14
// baseline (speedup 1.0000x reference)
#include <cuda_runtime.h>

// Problem constants
#define Bsz 64
#define Nn  27
#define Cc  512
#define Ee  729            // Nn*Nn
#define BNC (Bsz*Nn*Cc)    // 884736
#define BEC (Bsz*Ee*Cc)    // 23887872
#define EPSBN 1e-5f

// -------- scratch (device globals; no allocations allowed) --------
__device__ float g_Vix[BNC];
__device__ float g_Vjx[BNC];
__device__ float g_Uix[BNC];
__device__ float g_Ujx[BNC];
__device__ float g_xnew[BNC];
__device__ float g_x1[BNC];
__device__ float g_msg[BEC];     // e_lin, then msg in-place
__device__ float g_edge1[BEC];   // layer-1 edge output
__device__ float g_estats[2 * Ee]; // [mean(e)..., rstd(e)...]
__device__ float g_vstats[2 * Nn];

// ============================================================================
// SGEMM: Out[m,n] = sum_k A[m,k] * W[n,k]   (A:[M,512] rm, W:[512,512] rm)
// 64x64 tile, BK=16, 256 threads, 4x4 per-thread microtile.
// M and N are exact multiples of 64 for every call site -> no bounds checks.
// ============================================================================
__global__ __launch_bounds__(256) void sgemm_bt(const float* __restrict__ A,
                                                const float* __restrict__ W,
                                                float* __restrict__ Out) {
    __shared__ float As[16][64];
    __shared__ float Ws[16][64];
    const int tid = threadIdx.x;
    const int m0 = blockIdx.y * 64;
    const int n0 = blockIdx.x * 64;
    const int lr = tid >> 2;           // 0..63
    const int lk = (tid & 3) << 2;     // 0,4,8,12
    const int ty = tid >> 4;           // 0..15
    const int tx = tid & 15;           // 0..15

    const float* Ap = A + (m0 + lr) * 512 + lk;
    const float* Wp = W + (n0 + lr) * 512 + lk;

    float acc[4][4] = {};

    for (int k0 = 0; k0 < 512; k0 += 16) {
        float4 av = *(const float4*)(Ap + k0);
        float4 wv = *(const float4*)(Wp + k0);
        As[lk + 0][lr] = av.x; As[lk + 1][lr] = av.y;
        As[lk + 2][lr] = av.z; As[lk + 3][lr] = av.w;
        Ws[lk + 0][lr] = wv.x; Ws[lk + 1][lr] = wv.y;
        Ws[lk + 2][lr] = wv.z; Ws[lk + 3][lr] = wv.w;
        __syncthreads();
#pragma unroll
        for (int k = 0; k < 16; k++) {
            float a[4], w[4];
#pragma unroll
            for (int i = 0; i < 4; i++) a[i] = As[k][ty * 4 + i];
#pragma unroll
            for (int j = 0; j < 4; j++) w[j] = Ws[k][tx * 4 + j];
#pragma unroll
            for (int i = 0; i < 4; i++)
#pragma unroll
                for (int j = 0; j < 4; j++)
                    acc[i][j] = fmaf(a[i], w[j], acc[i][j]);
        }
        __syncthreads();
    }
#pragma unroll
    for (int i = 0; i < 4; i++) {
        float4 o = make_float4(acc[i][0], acc[i][1], acc[i][2], acc[i][3]);
        *(float4*)(Out + (m0 + ty * 4 + i) * 512 + n0 + tx * 4) = o;
    }
}

// ============================================================================
// Block reduce of (sum, sumsq) for 256-thread blocks.
// ============================================================================
__device__ __forceinline__ float2 block_reduce2(float s, float s2) {
    __shared__ float2 sh[8];
    int lane = threadIdx.x & 31, w = threadIdx.x >> 5;
#pragma unroll
    for (int o = 16; o; o >>= 1) {
        s  += __shfl_down_sync(0xffffffffu, s,  o);
        s2 += __shfl_down_sync(0xffffffffu, s2, o);
    }
    if (lane == 0) sh[w] = make_float2(s, s2);
    __syncthreads();
    float2 r = make_float2(0.f, 0.f);
    if (w == 0) {
        float2 v = (lane < 8) ? sh[lane] : make_float2(0.f, 0.f);
#pragma unroll
        for (int o = 4; o; o >>= 1) {
            v.x += __shfl_down_sync(0xffffffffu, v.x, o);
            v.y += __shfl_down_sync(0xffffffffu, v.y, o);
        }
        r = v;
    }
    return r; // valid in thread 0
}

// ============================================================================
// msg = e_lin + Vix[i] + Vjx[j] (in-place in g_msg) + per-edge BN stats.
// One block per edge index e; reduce over (batch, C) = 32768 elements.
// ============================================================================
__global__ __launch_bounds__(256) void msg_stats_k() {
    const int e = blockIdx.x;
    const int i = e / Nn, j = e % Nn;
    float4* mp = (float4*)g_msg;
    const float4* vi = (const float4*)g_Vix;
    const float4* vj = (const float4*)g_Vjx;
    float s = 0.f, s2 = 0.f;
    for (int t = threadIdx.x; t < Bsz * 128; t += 256) {
        const int b = t >> 7, c4 = t & 127;
        const int off = (b * Ee + e) * 128 + c4;
        float4 v = mp[off];
        float4 a = vi[(b * Nn + i) * 128 + c4];
        float4 bb = vj[(b * Nn + j) * 128 + c4];
        v.x += a.x + bb.x; v.y += a.y + bb.y;
        v.z += a.z + bb.z; v.w += a.w + bb.w;
        mp[off] = v;
        s  += v.x + v.y + v.z + v.w;
        s2 += v.x * v.x + v.y * v.y + v.z * v.z + v.w * v.w;
    }
    float2 r = block_reduce2(s, s2);
    if (threadIdx.x == 0) {
        const float inv = 1.f / (float)(Bsz * Cc);
        float mean = r.x * inv;
        float var = r.y * inv - mean * mean;
        g_estats[e] = mean;
        g_estats[Ee + e] = rsqrtf(var + EPSBN);
    }
}

// ============================================================================
// edge_out = edge_in + relu(bn(msg))   (float4 elementwise, BEC/4 lanes)
// ============================================================================
__global__ __launch_bounds__(256) void edge_update_k(const float* __restrict__ edge_in,
                                                     const float* __restrict__ ge,
                                                     const float* __restrict__ be,
                                                     float* __restrict__ edge_out) {
    const int idx4 = blockIdx.x * 256 + threadIdx.x;
    const int e = (idx4 >> 7) % Ee;
    const float mean = g_estats[e];
    const float rstd = g_estats[Ee + e];
    const float gsc = ge[e] * rstd;
    const float bsh = be[e] - mean * gsc;
    float4 m = ((const float4*)g_msg)[idx4];
    float4 x = ((const float4*)edge_in)[idx4];
    float4 o;
    o.x = x.x + fmaxf(fmaf(m.x, gsc, bsh), 0.f);
    o.y = x.y + fmaxf(fmaf(m.y, gsc, bsh), 0.f);
    o.z = x.z + fmaxf(fmaf(m.z, gsc, bsh), 0.f);
    o.w = x.w + fmaxf(fmaf(m.w, gsc, bsh), 0.f);
    ((float4*)edge_out)[idx4] = o;
}

// ============================================================================
// Attention + aggregation:
//   s[j]   = exp(sigmoid(edge[b, i*N+j, c]))
//   xnew   = Uix + (sum_j s[j]*Ujx[b,j,c]) / (sum_j s[j]) / N
// One thread per (b,i,c).
// ============================================================================
__global__ __launch_bounds__(256) void attn_agg_k(const float* __restrict__ edge) {
    const int idx = blockIdx.x * 256 + threadIdx.x;  // < BNC
    const int c = idx & 511;
    const int bi = idx >> 9;
    const int i = bi % Nn;
    const int b = bi / Nn;
    const float* ep = edge + (b * Ee + i * Nn) * 512 + c;
    const float* up = g_Ujx + (b * Nn) * 512 + c;
    float num = 0.f, den = 0.f;
#pragma unroll
    for (int j = 0; j < Nn; j++) {
        float v = ep[j * 512];
        float sg = 1.f / (1.f + __expf(-v));
        float s = __expf(sg);
        den += s;
        num = fmaf(s, up[j * 512], num);
    }
    g_xnew[idx] = g_Uix[idx] + num / (den * (float)Nn);
}

// ============================================================================
// Per-node BN stats over (batch, C).
// ============================================================================
__global__ __launch_bounds__(256) void vstats_k() {
    const int i = blockIdx.x;
    const float4* xp = (const float4*)g_xnew;
    float s = 0.f, s2 = 0.f;
    for (int t = threadIdx.x; t < Bsz * 128; t += 256) {
        const int b = t >> 7, c4 = t & 127;
        float4 v = xp[(b * Nn + i) * 128 + c4];
        s  += v.x + v.y + v.z + v.w;
        s2 += v.x * v.x + v.y * v.y + v.z * v.z + v.w * v.w;
    }
    float2 r = block_reduce2(s, s2);
    if (threadIdx.x == 0) {
        const float inv = 1.f / (float)(Bsz * Cc);
        float mean = r.x * inv;
        float var = r.y * inv - mean * mean;
        g_vstats[i] = mean;
        g_vstats[Nn + i] = rsqrtf(var + EPSBN);
    }
}

// ============================================================================
// x_out = relu(x_in + bn(xnew))   (float4 elementwise, BNC/4 lanes)
// ============================================================================
__global__ __launch_bounds__(256) void x_update_k(const float* __restrict__ x_in,
                                                  const float* __restrict__ gv,
                                                  const float* __restrict__ bv,
                                                  float* __restrict__ x_out) {
    const int idx4 = blockIdx.x * 256 + threadIdx.x;
    const int i = (idx4 >> 7) % Nn;
    const float mean = g_vstats[i];
    const float rstd = g_vstats[Nn + i];
    const float gsc = gv[i] * rstd;
    const float bsh = bv[i] - mean * gsc;
    float4 xn = ((const float4*)g_xnew)[idx4];
    float4 xi = ((const float4*)x_in)[idx4];
    float4 o;
    o.x = fmaxf(xi.x + fmaf(xn.x, gsc, bsh), 0.f);
    o.y = fmaxf(xi.y + fmaf(xn.y, gsc, bsh), 0.f);
    o.z = fmaxf(xi.z + fmaf(xn.z, gsc, bsh), 0.f);
    o.w = fmaxf(xi.w + fmaf(xn.w, gsc, bsh), 0.f);
    ((float4*)x_out)[idx4] = o;
}

// ============================================================================
// Host-side layer driver
// ============================================================================
static void run_layer(const float* x_in, const float* edge_in,
                      const float* WU, const float* WV, const float* WA,
                      const float* WB, const float* WE,
                      const float* gv, const float* bv,
                      const float* ge, const float* be,
                      float* x_out, float* edge_out,
                      float* pVix, float* pVjx, float* pUix, float* pUjx,
                      float* pmsg) {
    dim3 gN(8, 27);   // 1728 x 512
    dim3 gE(8, 729);  // 46656 x 512
    sgemm_bt<<<gN, 256>>>(x_in, WA, pVix);
    sgemm_bt<<<gN, 256>>>(x_in, WB, pVjx);
    sgemm_bt<<<gN, 256>>>(x_in, WU, pUix);
    sgemm_bt<<<gN, 256>>>(x_in, WV, pUjx);
    sgemm_bt<<<gE, 256>>>(edge_in, WE, pmsg);
    msg_stats_k<<<Ee, 256>>>();
    edge_update_k<<<BEC / 4 / 256, 256>>>(edge_in, ge, be, edge_out);
    attn_agg_k<<<BNC / 256, 256>>>(edge_out);
    vstats_k<<<Nn, 256>>>();
    x_update_k<<<BNC / 4 / 256, 256>>>(x_in, gv, bv, x_out);
}

extern "C" void kernel_launch(void* const* d_in, const int* in_sizes, int n_in,
                              void* d_out, int out_size) {
    const float* x    = (const float*)d_in[0];
    const float* edge = (const float*)d_in[1];
    const float* WU1 = (const float*)d_in[2];
    const float* WV1 = (const float*)d_in[3];
    const float* WA1 = (const float*)d_in[4];
    const float* WB1 = (const float*)d_in[5];
    const float* WE1 = (const float*)d_in[6];
    const float* WU2 = (const float*)d_in[7];
    const float* WV2 = (const float*)d_in[8];
    const float* WA2 = (const float*)d_in[9];
    const float* WB2 = (const float*)d_in[10];
    const float* WE2 = (const float*)d_in[11];
    const float* gv1 = (const float*)d_in[12];
    const float* bv1 = (const float*)d_in[13];
    const float* ge1 = (const float*)d_in[14];
    const float* be1 = (const float*)d_in[15];
    const float* gv2 = (const float*)d_in[16];
    const float* bv2 = (const float*)d_in[17];
    const float* ge2 = (const float*)d_in[18];
    const float* be2 = (const float*)d_in[19];

    float *pVix, *pVjx, *pUix, *pUjx, *pmsg, *px1, *pedge1;
    cudaGetSymbolAddress((void**)&pVix, g_Vix);
    cudaGetSymbolAddress((void**)&pVjx, g_Vjx);
    cudaGetSymbolAddress((void**)&pUix, g_Uix);
    cudaGetSymbolAddress((void**)&pUjx, g_Ujx);
    cudaGetSymbolAddress((void**)&pmsg, g_msg);
    cudaGetSymbolAddress((void**)&px1, g_x1);
    cudaGetSymbolAddress((void**)&pedge1, g_edge1);

    float* out = (float*)d_out;
    float* x2_out = out;          // x:   [64,27,512]
    float* e2_out = out + BNC;    // edge:[64,729,512]

    run_layer(x, edge, WU1, WV1, WA1, WB1, WE1, gv1, bv1, ge1, be1,
              px1, pedge1, pVix, pVjx, pUix, pUjx, pmsg);
    run_layer(px1, pedge1, WU2, WV2, WA2, WB2, WE2, gv2, bv2, ge2, be2,
              x2_out, e2_out, pVix, pVjx, pUix, pUjx, pmsg);
}

// round 15
// speedup vs baseline: 1.1760x; 1.1760x over previous
#include <cuda_runtime.h>

// Problem constants
#define Bsz 64
#define Nn  27
#define Cc  512
#define Ee  729            // Nn*Nn
#define BNC (Bsz*Nn*Cc)    // 884736
#define BEC (Bsz*Ee*Cc)    // 23887872
#define EPSBN 1e-5f

// -------- scratch (device globals; no allocations allowed) --------
__device__ float g_node4[4 * BNC];   // [Vix | Vjx | Uix | Ujx]
__device__ float g_xnew[BNC];
__device__ float g_x1[BNC];
__device__ float g_msg[BEC];
__device__ float g_edge1[BEC];
__device__ float g_esum[Ee];
__device__ float g_esq[Ee];
__device__ float g_estats[2 * Ee];   // [mean | rstd]
__device__ float g_vstats[2 * Nn];

// ---------------- f32x2 helpers ----------------
__device__ __forceinline__ void fma2(unsigned long long& d,
                                     unsigned long long a,
                                     unsigned long long b) {
    asm("fma.rn.f32x2 %0, %1, %2, %0;" : "+l"(d) : "l"(a), "l"(b));
}
__device__ __forceinline__ unsigned long long splat2(float f) {
    unsigned long long r;
    unsigned u = __float_as_uint(f);
    asm("mov.b64 %0, {%1, %1};" : "=l"(r) : "r"(u));
    return r;
}
__device__ __forceinline__ float f2lo(unsigned long long v) {
    return __uint_as_float((unsigned)v);
}
__device__ __forceinline__ float f2hi(unsigned long long v) {
    return __uint_as_float((unsigned)(v >> 32));
}

// ============================================================================
// f32x2 SGEMM: Out[m,n] = sum_k A[m,k]*W[n,k].  64x128 tile, BK=16,
// 128 threads, 8x8 microtile (m packed in pairs into f32x2 lanes).
// MODE 0: node GEMM, 4 weights fused (blockIdx.x>>2 selects W and out slab).
// MODE 1: edge GEMM with fused epilogue:
//         msg = gemm + Vix[b,i] + Vjx[b,j], write msg, atomic BN stats per e.
// ============================================================================
template<int MODE>
__global__ __launch_bounds__(128) void gemm_f32x2(
    const float* __restrict__ A,
    const float* __restrict__ W0, const float* __restrict__ W1,
    const float* __restrict__ W2, const float* __restrict__ W3,
    float* __restrict__ out,
    const float* __restrict__ node4,
    float* __restrict__ esum, float* __restrict__ esq)
{
    __align__(16) __shared__ float As[2][16][64];
    __align__(16) __shared__ float Wsh[2][16][128];

    const int tid = threadIdx.x;
    const int tx = tid & 15;          // n-thread (0..15)
    const int ty = tid >> 4;          // m-thread (0..7)
    const int m0 = blockIdx.y * 64;

    int n0;
    const float* W;
    if (MODE == 0) {
        const int widx = blockIdx.x >> 2;
        n0 = (blockIdx.x & 3) * 128;
        W = (widx == 0) ? W0 : (widx == 1) ? W1 : (widx == 2) ? W2 : W3;
        out += (size_t)widx * BNC;
    } else {
        n0 = blockIdx.x * 128;
        W = W0;
    }

    // staging assignments
    const int ar = tid >> 1;            // A row in tile (0..63)
    const int ak = (tid & 1) << 3;      // A k offset (0 or 8)
    const float* Ap = A + (size_t)(m0 + ar) * 512 + ak;
    const float* Wp = W + (size_t)(n0 + tid) * 512;

    float4 aR0, aR1, wR0, wR1, wR2, wR3;

    // prologue: k-tile 0
    aR0 = *(const float4*)(Ap);
    aR1 = *(const float4*)(Ap + 4);
    wR0 = *(const float4*)(Wp);
    wR1 = *(const float4*)(Wp + 4);
    wR2 = *(const float4*)(Wp + 8);
    wR3 = *(const float4*)(Wp + 12);
    As[0][ak + 0][ar] = aR0.x; As[0][ak + 1][ar] = aR0.y;
    As[0][ak + 2][ar] = aR0.z; As[0][ak + 3][ar] = aR0.w;
    As[0][ak + 4][ar] = aR1.x; As[0][ak + 5][ar] = aR1.y;
    As[0][ak + 6][ar] = aR1.z; As[0][ak + 7][ar] = aR1.w;
    Wsh[0][0][tid]  = wR0.x; Wsh[0][1][tid]  = wR0.y; Wsh[0][2][tid]  = wR0.z; Wsh[0][3][tid]  = wR0.w;
    Wsh[0][4][tid]  = wR1.x; Wsh[0][5][tid]  = wR1.y; Wsh[0][6][tid]  = wR1.z; Wsh[0][7][tid]  = wR1.w;
    Wsh[0][8][tid]  = wR2.x; Wsh[0][9][tid]  = wR2.y; Wsh[0][10][tid] = wR2.z; Wsh[0][11][tid] = wR2.w;
    Wsh[0][12][tid] = wR3.x; Wsh[0][13][tid] = wR3.y; Wsh[0][14][tid] = wR3.z; Wsh[0][15][tid] = wR3.w;
    __syncthreads();

    unsigned long long acc[4][8];
#pragma unroll
    for (int i = 0; i < 4; i++)
#pragma unroll
        for (int j = 0; j < 8; j++) acc[i][j] = 0ULL;

    for (int t = 0; t < 32; t++) {
        const int cur = t & 1;
        if (t < 31) {
            const int ko = (t + 1) * 16;
            aR0 = *(const float4*)(Ap + ko);
            aR1 = *(const float4*)(Ap + ko + 4);
            wR0 = *(const float4*)(Wp + ko);
            wR1 = *(const float4*)(Wp + ko + 4);
            wR2 = *(const float4*)(Wp + ko + 8);
            wR3 = *(const float4*)(Wp + ko + 12);
        }
#pragma unroll
        for (int kk = 0; kk < 16; kk++) {
            ulonglong2 a01 = *reinterpret_cast<const ulonglong2*>(&As[cur][kk][ty * 8]);
            ulonglong2 a23 = *reinterpret_cast<const ulonglong2*>(&As[cur][kk][ty * 8 + 4]);
            float4 w0 = *reinterpret_cast<const float4*>(&Wsh[cur][kk][tx * 8]);
            float4 w1 = *reinterpret_cast<const float4*>(&Wsh[cur][kk][tx * 8 + 4]);
            unsigned long long ws[8];
            ws[0] = splat2(w0.x); ws[1] = splat2(w0.y); ws[2] = splat2(w0.z); ws[3] = splat2(w0.w);
            ws[4] = splat2(w1.x); ws[5] = splat2(w1.y); ws[6] = splat2(w1.z); ws[7] = splat2(w1.w);
            unsigned long long ap[4] = {a01.x, a01.y, a23.x, a23.y};
#pragma unroll
            for (int mp = 0; mp < 4; mp++)
#pragma unroll
                for (int n = 0; n < 8; n++)
                    fma2(acc[mp][n], ap[mp], ws[n]);
        }
        if (t < 31) {
            const int nb = cur ^ 1;
            As[nb][ak + 0][ar] = aR0.x; As[nb][ak + 1][ar] = aR0.y;
            As[nb][ak + 2][ar] = aR0.z; As[nb][ak + 3][ar] = aR0.w;
            As[nb][ak + 4][ar] = aR1.x; As[nb][ak + 5][ar] = aR1.y;
            As[nb][ak + 6][ar] = aR1.z; As[nb][ak + 7][ar] = aR1.w;
            Wsh[nb][0][tid]  = wR0.x; Wsh[nb][1][tid]  = wR0.y; Wsh[nb][2][tid]  = wR0.z; Wsh[nb][3][tid]  = wR0.w;
            Wsh[nb][4][tid]  = wR1.x; Wsh[nb][5][tid]  = wR1.y; Wsh[nb][6][tid]  = wR1.z; Wsh[nb][7][tid]  = wR1.w;
            Wsh[nb][8][tid]  = wR2.x; Wsh[nb][9][tid]  = wR2.y; Wsh[nb][10][tid] = wR2.z; Wsh[nb][11][tid] = wR2.w;
            Wsh[nb][12][tid] = wR3.x; Wsh[nb][13][tid] = wR3.y; Wsh[nb][14][tid] = wR3.z; Wsh[nb][15][tid] = wR3.w;
            __syncthreads();
        }
    }

    const int col0 = n0 + tx * 8;

    if (MODE == 0) {
#pragma unroll
        for (int mp = 0; mp < 4; mp++) {
            const int rlo = m0 + ty * 8 + mp * 2;
            float4 v0, v1;
            v0.x = f2lo(acc[mp][0]); v0.y = f2lo(acc[mp][1]);
            v0.z = f2lo(acc[mp][2]); v0.w = f2lo(acc[mp][3]);
            v1.x = f2lo(acc[mp][4]); v1.y = f2lo(acc[mp][5]);
            v1.z = f2lo(acc[mp][6]); v1.w = f2lo(acc[mp][7]);
            *(float4*)(out + (size_t)rlo * 512 + col0) = v0;
            *(float4*)(out + (size_t)rlo * 512 + col0 + 4) = v1;
            v0.x = f2hi(acc[mp][0]); v0.y = f2hi(acc[mp][1]);
            v0.z = f2hi(acc[mp][2]); v0.w = f2hi(acc[mp][3]);
            v1.x = f2hi(acc[mp][4]); v1.y = f2hi(acc[mp][5]);
            v1.z = f2hi(acc[mp][6]); v1.w = f2hi(acc[mp][7]);
            *(float4*)(out + (size_t)(rlo + 1) * 512 + col0) = v0;
            *(float4*)(out + (size_t)(rlo + 1) * 512 + col0 + 4) = v1;
        }
    } else {
        // fused msg epilogue: add Vix[b,i] + Vjx[b,j], store msg, atomic stats
#pragma unroll
        for (int mp = 0; mp < 4; mp++) {
#pragma unroll
            for (int half = 0; half < 2; half++) {
                const int r = m0 + ty * 8 + mp * 2 + half;
                const int b = r / Ee;
                const int e = r - b * Ee;
                const int i = e / Nn;
                const int j = e - i * Nn;
                const float4* vi = (const float4*)(node4 + (size_t)(b * Nn + i) * 512 + col0);
                const float4* vj = (const float4*)(node4 + BNC + (size_t)(b * Nn + j) * 512 + col0);
                float4 vi0 = vi[0], vi1 = vi[1];
                float4 vj0 = vj[0], vj1 = vj[1];
                float v[8];
                if (half == 0) {
#pragma unroll
                    for (int n = 0; n < 8; n++) v[n] = f2lo(acc[mp][n]);
                } else {
#pragma unroll
                    for (int n = 0; n < 8; n++) v[n] = f2hi(acc[mp][n]);
                }
                v[0] += vi0.x + vj0.x; v[1] += vi0.y + vj0.y;
                v[2] += vi0.z + vj0.z; v[3] += vi0.w + vj0.w;
                v[4] += vi1.x + vj1.x; v[5] += vi1.y + vj1.y;
                v[6] += vi1.z + vj1.z; v[7] += vi1.w + vj1.w;
                float4 o0 = make_float4(v[0], v[1], v[2], v[3]);
                float4 o1 = make_float4(v[4], v[5], v[6], v[7]);
                *(float4*)(out + (size_t)r * 512 + col0) = o0;
                *(float4*)(out + (size_t)r * 512 + col0 + 4) = o1;
                float s = 0.f, q = 0.f;
#pragma unroll
                for (int n = 0; n < 8; n++) { s += v[n]; q += v[n] * v[n]; }
#pragma unroll
                for (int off = 8; off; off >>= 1) {
                    s += __shfl_down_sync(0xffffffffu, s, off, 16);
                    q += __shfl_down_sync(0xffffffffu, q, off, 16);
                }
                if (tx == 0) {
                    atomicAdd(&esum[e], s);
                    atomicAdd(&esq[e], q);
                }
            }
        }
    }
}

// ============================================================================
// Small helper kernels
// ============================================================================
__global__ void zero_stats_k() {
    const int e = threadIdx.x;
    if (e < Ee) { g_esum[e] = 0.f; g_esq[e] = 0.f; }
}

__global__ void estats_fin_k() {
    const int e = blockIdx.x * 256 + threadIdx.x;
    if (e < Ee) {
        const float inv = 1.f / (float)(Bsz * Cc);
        float m = g_esum[e] * inv;
        float var = g_esq[e] * inv - m * m;
        g_estats[e] = m;
        g_estats[Ee + e] = rsqrtf(var + EPSBN);
    }
}

// edge_out = edge_in + relu(bn(msg))
__global__ __launch_bounds__(256) void edge_update_k(const float* __restrict__ edge_in,
                                                     const float* __restrict__ ge,
                                                     const float* __restrict__ be,
                                                     float* __restrict__ edge_out) {
    const int idx4 = blockIdx.x * 256 + threadIdx.x;
    const int e = (idx4 >> 7) % Ee;
    const float mean = g_estats[e];
    const float rstd = g_estats[Ee + e];
    const float gsc = ge[e] * rstd;
    const float bsh = be[e] - mean * gsc;
    float4 m = ((const float4*)g_msg)[idx4];
    float4 x = ((const float4*)edge_in)[idx4];
    float4 o;
    o.x = x.x + fmaxf(fmaf(m.x, gsc, bsh), 0.f);
    o.y = x.y + fmaxf(fmaf(m.y, gsc, bsh), 0.f);
    o.z = x.z + fmaxf(fmaf(m.z, gsc, bsh), 0.f);
    o.w = x.w + fmaxf(fmaf(m.w, gsc, bsh), 0.f);
    ((float4*)edge_out)[idx4] = o;
}

// attention + aggregation
__global__ __launch_bounds__(256) void attn_agg_k(const float* __restrict__ edge,
                                                  const float* __restrict__ uix,
                                                  const float* __restrict__ ujx) {
    const int idx = blockIdx.x * 256 + threadIdx.x;  // < BNC
    const int c = idx & 511;
    const int bi = idx >> 9;
    const int i = bi % Nn;
    const int b = bi / Nn;
    const float* ep = edge + ((size_t)b * Ee + i * Nn) * 512 + c;
    const float* up = ujx + (size_t)(b * Nn) * 512 + c;
    float num = 0.f, den = 0.f;
#pragma unroll
    for (int j = 0; j < Nn; j++) {
        float v = ep[j * 512];
        float sg = 1.f / (1.f + __expf(-v));
        float s = __expf(sg);
        den += s;
        num = fmaf(s, up[j * 512], num);
    }
    g_xnew[idx] = uix[idx] + num / (den * (float)Nn);
}

__device__ __forceinline__ float2 block_reduce2(float s, float s2) {
    __shared__ float2 sh[8];
    int lane = threadIdx.x & 31, w = threadIdx.x >> 5;
#pragma unroll
    for (int o = 16; o; o >>= 1) {
        s  += __shfl_down_sync(0xffffffffu, s,  o);
        s2 += __shfl_down_sync(0xffffffffu, s2, o);
    }
    if (lane == 0) sh[w] = make_float2(s, s2);
    __syncthreads();
    float2 r = make_float2(0.f, 0.f);
    if (w == 0) {
        float2 v = (lane < 8) ? sh[lane] : make_float2(0.f, 0.f);
#pragma unroll
        for (int o = 4; o; o >>= 1) {
            v.x += __shfl_down_sync(0xffffffffu, v.x, o);
            v.y += __shfl_down_sync(0xffffffffu, v.y, o);
        }
        r = v;
    }
    return r;
}

__global__ __launch_bounds__(256) void vstats_k() {
    const int i = blockIdx.x;
    const float4* xp = (const float4*)g_xnew;
    float s = 0.f, s2 = 0.f;
    for (int t = threadIdx.x; t < Bsz * 128; t += 256) {
        const int b = t >> 7, c4 = t & 127;
        float4 v = xp[(b * Nn + i) * 128 + c4];
        s  += v.x + v.y + v.z + v.w;
        s2 += v.x * v.x + v.y * v.y + v.z * v.z + v.w * v.w;
    }
    float2 r = block_reduce2(s, s2);
    if (threadIdx.x == 0) {
        const float inv = 1.f / (float)(Bsz * Cc);
        float mean = r.x * inv;
        float var = r.y * inv - mean * mean;
        g_vstats[i] = mean;
        g_vstats[Nn + i] = rsqrtf(var + EPSBN);
    }
}

__global__ __launch_bounds__(256) void x_update_k(const float* __restrict__ x_in,
                                                  const float* __restrict__ gv,
                                                  const float* __restrict__ bv,
                                                  float* __restrict__ x_out) {
    const int idx4 = blockIdx.x * 256 + threadIdx.x;
    const int i = (idx4 >> 7) % Nn;
    const float mean = g_vstats[i];
    const float rstd = g_vstats[Nn + i];
    const float gsc = gv[i] * rstd;
    const float bsh = bv[i] - mean * gsc;
    float4 xn = ((const float4*)g_xnew)[idx4];
    float4 xi = ((const float4*)x_in)[idx4];
    float4 o;
    o.x = fmaxf(xi.x + fmaf(xn.x, gsc, bsh), 0.f);
    o.y = fmaxf(xi.y + fmaf(xn.y, gsc, bsh), 0.f);
    o.z = fmaxf(xi.z + fmaf(xn.z, gsc, bsh), 0.f);
    o.w = fmaxf(xi.w + fmaf(xn.w, gsc, bsh), 0.f);
    ((float4*)x_out)[idx4] = o;
}

// ============================================================================
// Host-side layer driver
// ============================================================================
static void run_layer(const float* x_in, const float* edge_in,
                      const float* WU, const float* WV, const float* WA,
                      const float* WB, const float* WE,
                      const float* gv, const float* bv,
                      const float* ge, const float* be,
                      float* x_out, float* edge_out,
                      float* pnode4, float* pmsg, float* pesum, float* pesq) {
    zero_stats_k<<<1, 768>>>();
    // node GEMMs fused: slabs [Vix | Vjx | Uix | Ujx]
    gemm_f32x2<0><<<dim3(16, 27), 128>>>(x_in, WA, WB, WU, WV,
                                         pnode4, nullptr, nullptr, nullptr);
    // edge GEMM with fused msg epilogue + BN-stat atomics
    gemm_f32x2<1><<<dim3(4, 729), 128>>>(edge_in, WE, WE, WE, WE,
                                         pmsg, pnode4, pesum, pesq);
    estats_fin_k<<<3, 256>>>();
    edge_update_k<<<BEC / 4 / 256, 256>>>(edge_in, ge, be, edge_out);
    attn_agg_k<<<BNC / 256, 256>>>(edge_out, pnode4 + 2 * (size_t)BNC,
                                   pnode4 + 3 * (size_t)BNC);
    vstats_k<<<Nn, 256>>>();
    x_update_k<<<BNC / 4 / 256, 256>>>(x_in, gv, bv, x_out);
}

extern "C" void kernel_launch(void* const* d_in, const int* in_sizes, int n_in,
                              void* d_out, int out_size) {
    const float* x    = (const float*)d_in[0];
    const float* edge = (const float*)d_in[1];
    const float* WU1 = (const float*)d_in[2];
    const float* WV1 = (const float*)d_in[3];
    const float* WA1 = (const float*)d_in[4];
    const float* WB1 = (const float*)d_in[5];
    const float* WE1 = (const float*)d_in[6];
    const float* WU2 = (const float*)d_in[7];
    const float* WV2 = (const float*)d_in[8];
    const float* WA2 = (const float*)d_in[9];
    const float* WB2 = (const float*)d_in[10];
    const float* WE2 = (const float*)d_in[11];
    const float* gv1 = (const float*)d_in[12];
    const float* bv1 = (const float*)d_in[13];
    const float* ge1 = (const float*)d_in[14];
    const float* be1 = (const float*)d_in[15];
    const float* gv2 = (const float*)d_in[16];
    const float* bv2 = (const float*)d_in[17];
    const float* ge2 = (const float*)d_in[18];
    const float* be2 = (const float*)d_in[19];

    float *pnode4, *pmsg, *px1, *pedge1, *pesum, *pesq;
    cudaGetSymbolAddress((void**)&pnode4, g_node4);
    cudaGetSymbolAddress((void**)&pmsg, g_msg);
    cudaGetSymbolAddress((void**)&px1, g_x1);
    cudaGetSymbolAddress((void**)&pedge1, g_edge1);
    cudaGetSymbolAddress((void**)&pesum, g_esum);
    cudaGetSymbolAddress((void**)&pesq, g_esq);

    float* out = (float*)d_out;
    float* x2_out = out;          // x:   [64,27,512]
    float* e2_out = out + BNC;    // edge:[64,729,512]

    run_layer(x, edge, WU1, WV1, WA1, WB1, WE1, gv1, bv1, ge1, be1,
              px1, pedge1, pnode4, pmsg, pesum, pesq);
    run_layer(px1, pedge1, WU2, WV2, WA2, WB2, WE2, gv2, bv2, ge2, be2,
              x2_out, e2_out, pnode4, pmsg, pesum, pesq);
}